// round 16
// baseline (speedup 1.0000x reference)
#include <cuda_runtime.h>
#include <cuda_bf16.h>
#include <math.h>
#include <stdint.h>

// ---------------------------------------------------------------------------
// FastKAN 3-layer conv net — HMMA (mma.sync bf16), warp-independent.
// R16 = R15 + dense-28 K packing: 28 slots/feature (27 used + 1 pad) vs 32.
//   chunk = 112 slots = 4 features = 7 k16 steps (fixed compile-time layout).
//   A tile rows: 224B used / 256B pitch, swizzle on 16x16B units.
//   -12.5% HMMA instructions and B traffic; numerics identical.
// ---------------------------------------------------------------------------

#define MAXF_STAT (131072)
#define MAXF_CONV (131072 * 64)
#define MAXF_X1   (32 * 64 * 32 * 32)
#define MAXF_X2   (32 * 128 * 16 * 16)
#define MAX_WTB32 (1152 * 14 * 256)

__device__ float g_mu[MAXF_STAT];
__device__ float g_rstd[MAXF_STAT];
__device__ uint32_t g_wtb[MAX_WTB32];
__device__ float g_conv[MAXF_CONV];
__device__ float g_x1[MAXF_X1];
__device__ float g_x2[MAXF_X2];
__device__ float g_bn[2 * 256];

// ------------------------------ helpers -----------------------------------
__device__ __forceinline__ uint32_t s2u(const void* p) {
    uint32_t a;
    asm("{ .reg .u64 t; cvta.to.shared.u64 t, %1; cvt.u32.u64 %0, t; }"
        : "=r"(a) : "l"(p));
    return a;
}
__device__ __forceinline__ void ldmatrix_x4(uint32_t* r, uint32_t addr) {
    asm volatile("ldmatrix.sync.aligned.m8n8.x4.shared.b16 {%0,%1,%2,%3}, [%4];"
                 : "=r"(r[0]), "=r"(r[1]), "=r"(r[2]), "=r"(r[3]) : "r"(addr));
}
__device__ __forceinline__ void mma16816(float* c, const uint32_t* a,
                                         uint32_t b0, uint32_t b1) {
    asm volatile(
        "mma.sync.aligned.m16n8k16.row.col.f32.bf16.bf16.f32 "
        "{%0,%1,%2,%3}, {%4,%5,%6,%7}, {%8,%9}, {%0,%1,%2,%3};"
        : "+f"(c[0]), "+f"(c[1]), "+f"(c[2]), "+f"(c[3])
        : "r"(a[0]), "r"(a[1]), "r"(a[2]), "r"(a[3]), "r"(b0), "r"(b1));
}
// swizzled address of byte offset `off` (0..255) in row m (256B pitch)
__device__ __forceinline__ uint32_t swaddr(uint32_t Ab, int m, int off) {
    int ci = off >> 4, rem = off & 15;
    return Ab + (uint32_t)m * 256
         + (uint32_t)(((ci & 8) | ((ci ^ (m & 7)) & 7)) << 4) + rem;
}

// ---------------------------------------------------------------------------
// 1) per-pixel LayerNorm stats (mu, rstd). One warp per pixel.
// ---------------------------------------------------------------------------
__global__ void prep_stats_kernel(const float* __restrict__ x,
                                  float* __restrict__ mu_o,
                                  float* __restrict__ rstd_o,
                                  int C, int H, int W, int fin, int N)
{
    int warp = (blockIdx.x * blockDim.x + threadIdx.x) >> 5;
    int lane = threadIdx.x & 31;
    if (warp >= N) return;
    int w = warp % W;
    int h = (warp / W) % H;
    int b = warp / (W * H);
    const float* xb = x + (size_t)b * C * H * W;

    float s = 0.f, s2 = 0.f;
    for (int f = lane; f < fin; f += 32) {
        int c = f / 9, r = f - c * 9;
        int hh = h + r / 3 - 1, ww = w + (r % 3) - 1;
        float v = 0.f;
        if (hh >= 0 && hh < H && ww >= 0 && ww < W)
            v = xb[(c * H + hh) * W + ww];
        s += v; s2 += v * v;
    }
#pragma unroll
    for (int o = 16; o; o >>= 1) {
        s  += __shfl_xor_sync(0xffffffffu, s,  o);
        s2 += __shfl_xor_sync(0xffffffffu, s2, o);
    }
    if (lane == 0) {
        float inv  = 1.f / (float)fin;
        float mu   = s * inv;
        float var  = fmaxf(s2 * inv - mu * mu, 0.f);
        mu_o[warp]   = mu;
        rstd_o[warp] = rsqrtf(var + 1e-5f);
    }
}

// ---------------------------------------------------------------------------
// 2) weight prep: pack B in HMMA fragment order, dense-28 K (28 slots/feat).
// ---------------------------------------------------------------------------
__global__ void wtrans_frag_kernel(const float* __restrict__ Wb,
                                   const float* __restrict__ Ws,
                                   uint32_t* __restrict__ wtb,
                                   int fin, int fout)
{
    int idx = blockIdx.x * blockDim.x + threadIdx.x;
    int nt = fout >> 3;
    int total = fin * 14 * fout;            // b32 count: K = 28*fin
    if (idx >= total) return;
    int r  = idx & 1;
    int l  = (idx >> 1) & 31;
    int tg = (idx >> 6) % nt;
    int cs = idx / (64 * nt);
    int n  = tg * 8 + (l >> 2);
    int k0 = cs * 16 + (l & 3) * 2 + r * 8;

    float f2[2];
#pragma unroll
    for (int e = 0; e < 2; e++) {
        int k = k0 + e;
        int i = k / 28, slot = k - i * 28;
        float v = 0.f;
        if (slot < 27) {
            int t9 = slot / 3, term = slot % 3;
            float w = (t9 == 0) ? Wb[(size_t)n * fin + i]
                                : Ws[(size_t)n * fin * 8 + i * 8 + (t9 - 1)];
            __nv_bfloat16 h = __float2bfloat16(w);
            v = (term == 1) ? (w - __bfloat162float(h)) : __bfloat162float(h);
        }
        f2[e] = v;
    }
    __nv_bfloat162 p;
    p.x = __float2bfloat16(f2[0]);
    p.y = __float2bfloat16(f2[1]);
    wtb[idx] = *(uint32_t*)&p;
}

// ---------------------------------------------------------------------------
// 3) fused KAN HMMA kernel — dense-28, chunk = 4 features = 7 k16 steps.
//    MROWS=32: 128-thread CTAs, warp owns 32 rows, lane expands 4 features.
//    MROWS=16: 256-thread CTAs, warp owns 16 rows, lane expands 2 features.
//    CTA covers 128 rows x 64 cols; A tile 128 x 256B (32 KB).
// ---------------------------------------------------------------------------
template<int MROWS>
__global__ __launch_bounds__(4096 / MROWS, MROWS == 32 ? 4 : 2)
void kan_mma_kernel(const float* __restrict__ x,
                    const float* __restrict__ mu_a,
                    const float* __restrict__ rstd_a,
                    const float* __restrict__ lnw,
                    const float* __restrict__ lnb,
                    const uint32_t* __restrict__ wtb,
                    const float* __restrict__ bb,
                    float* __restrict__ out,
                    int Cin, int H, int W, int fin, int fout)
{
    constexpr int MT = MROWS / 16;           // m16 tiles per warp
    constexpr int EF = (MROWS == 32) ? 4 : 2; // features expanded per lane
    __shared__ __align__(1024) char As[128 * 256];   // 32 KB

    int tid  = threadIdx.x;
    int lane = tid & 31;
    int wid  = tid >> 5;
    int row0 = blockIdx.x * 128;
    int n0   = blockIdx.y * 64;
    int wrow = wid * MROWS;
    int ntglob = fout >> 3;
    int n0g = n0 >> 3;
    uint32_t Ab = s2u(As);

    float acc[MT][8][4];
#pragma unroll
    for (int mt = 0; mt < MT; mt++)
#pragma unroll
        for (int t = 0; t < 8; t++)
#pragma unroll
            for (int q = 0; q < 4; q++) acc[mt][t][q] = 0.f;

    // expansion task: fixed pixel per lane
    int erow  = (MROWS == 32) ? lane : (lane & 15);
    int fhalf = (MROWS == 32) ? 0    : (lane >> 4);   // placement base /2
    int m    = wrow + erow;
    int npix = row0 + m;
    int wpix = npix % W;
    int hpix = (npix / W) % H;
    int bpix = npix / (W * H);
    float mu_v = mu_a[npix];
    float rs_v = rstd_a[npix];
    const float* xb = x + (size_t)bpix * Cin * H * W;

    int j = lane >> 3, rr2 = lane & 7;
    int C = fin >> 2;            // chunks (4 features each)

    auto gather = [&](int f) -> float {
        int cch = f / 9, r = f - cch * 9;
        int hh = hpix + r / 3 - 1, ww = wpix + (r % 3) - 1;
        float v = 0.f;
        if (hh >= 0 && hh < H && ww >= 0 && ww < W)
            v = xb[(cch * H + hh) * W + ww];
        return v;
    };

    float v_next[EF];
#pragma unroll
    for (int fi = 0; fi < EF; fi++)
        v_next[fi] = gather(2 * fhalf + fi);

    for (int c = 0; c < C; c++) {
        // ---------- expand chunk c (4 features, dense-28) ----------
#pragma unroll
        for (int fi = 0; fi < EF; fi++) {
            int fplace = 2 * fhalf + fi;          // 0..3 within chunk
            int f = 4 * c + fplace;
            float v  = v_next[fi];
            float xv = (v - mu_v) * rs_v * __ldg(&lnw[f]) + __ldg(&lnb[f]);
            float sv = v / (1.f + __expf(-v));

            const float q = 0.13533528323661270f;   // exp(-2)
            float d  = fmaf(xv, 1.75f, -0.5f);       // u-4, u=1.75x+3.5
            float e4 = __expf(-d * d);
            float R  = __expf(fmaf( 2.f, d, -1.f));
            float S  = __expf(fmaf(-2.f, d, -1.f));
            float e5 = e4 * R;  R *= q;
            float e6 = e5 * R;  R *= q;
            float e7 = e6 * R;
            float e3 = e4 * S;  S *= q;
            float e2 = e3 * S;  S *= q;
            float e1 = e2 * S;  S *= q;
            float e0 = e1 * S;

            float vals[9] = { sv, e0, e1, e2, e3, e4, e5, e6, e7 };

            uint32_t vb[9], lb[9];
#pragma unroll
            for (int t9 = 0; t9 < 9; t9++) {
                uint32_t b = __float_as_uint(vals[t9]);
                vb[t9] = b;
                float hf = __uint_as_float(b & 0xFFFF0000u);
                lb[t9] = (uint32_t)__bfloat16_as_ushort(
                             __float2bfloat16(vals[t9] - hf));
            }
            uint32_t w[14];
#pragma unroll
            for (int p = 0; p < 4; p++) {
                w[3 * p + 0] = __byte_perm(vb[2 * p],     vb[2 * p],     0x3232);
                w[3 * p + 1] = __byte_perm(lb[2 * p],     vb[2 * p + 1], 0x7610);
                w[3 * p + 2] = __byte_perm(vb[2 * p + 1], lb[2 * p + 1], 0x5432);
            }
            w[12] = __byte_perm(vb[8], vb[8], 0x3232);
            w[13] = lb[8];

            int base = fplace * 56;               // byte offset in row
            if ((fplace & 1) == 0) {
                asm volatile("st.shared.v4.b32 [%0], {%1,%2,%3,%4};"
                    :: "r"(swaddr(Ab, m, base + 0)),  "r"(w[0]), "r"(w[1]), "r"(w[2]), "r"(w[3]));
                asm volatile("st.shared.v4.b32 [%0], {%1,%2,%3,%4};"
                    :: "r"(swaddr(Ab, m, base + 16)), "r"(w[4]), "r"(w[5]), "r"(w[6]), "r"(w[7]));
                asm volatile("st.shared.v4.b32 [%0], {%1,%2,%3,%4};"
                    :: "r"(swaddr(Ab, m, base + 32)), "r"(w[8]), "r"(w[9]), "r"(w[10]), "r"(w[11]));
                asm volatile("st.shared.v2.b32 [%0], {%1,%2};"
                    :: "r"(swaddr(Ab, m, base + 48)), "r"(w[12]), "r"(w[13]));
            } else {
                asm volatile("st.shared.v2.b32 [%0], {%1,%2};"
                    :: "r"(swaddr(Ab, m, base + 0)),  "r"(w[0]), "r"(w[1]));
                asm volatile("st.shared.v4.b32 [%0], {%1,%2,%3,%4};"
                    :: "r"(swaddr(Ab, m, base + 8)),  "r"(w[2]), "r"(w[3]), "r"(w[4]), "r"(w[5]));
                asm volatile("st.shared.v4.b32 [%0], {%1,%2,%3,%4};"
                    :: "r"(swaddr(Ab, m, base + 24)), "r"(w[6]), "r"(w[7]), "r"(w[8]), "r"(w[9]));
                asm volatile("st.shared.v4.b32 [%0], {%1,%2,%3,%4};"
                    :: "r"(swaddr(Ab, m, base + 40)), "r"(w[10]), "r"(w[11]), "r"(w[12]), "r"(w[13]));
            }
        }
        __syncwarp();
        // prefetch next chunk's taps; MMA below covers their latency
        if (c + 1 < C) {
#pragma unroll
            for (int fi = 0; fi < EF; fi++)
                v_next[fi] = gather(4 * (c + 1) + 2 * fhalf + fi);
        }
        // ---------- MMA chunk c: 7 k16 steps, B double-buffered ----------
        {
            uint2 bf[2][8];
            {
                const uint2* bp = (const uint2*)wtb
                                + ((size_t)(c * 7) * ntglob + n0g) * 32 + lane;
#pragma unroll
                for (int t = 0; t < 8; t++) bf[0][t] = __ldg(bp + t * 32);
            }
#pragma unroll
            for (int s = 0; s < 7; s++) {
                if (s < 6) {
                    const uint2* bp = (const uint2*)wtb
                                    + ((size_t)(c * 7 + s + 1) * ntglob + n0g) * 32 + lane;
#pragma unroll
                    for (int t = 0; t < 8; t++) bf[(s + 1) & 1][t] = __ldg(bp + t * 32);
                }
#pragma unroll
                for (int mt = 0; mt < MT; mt++) {
                    uint32_t af[4];
                    int arow = wrow + mt * 16 + (j & 1) * 8 + rr2;
                    int qcol = s * 2 + (j >> 1);        // 0..13
                    uint32_t ad = Ab + (uint32_t)arow * 256
                        + (uint32_t)(((qcol & 8) | ((qcol ^ (arow & 7)) & 7)) << 4);
                    ldmatrix_x4(af, ad);
#pragma unroll
                    for (int t = 0; t < 8; t++)
                        mma16816(acc[mt][t], af, bf[s & 1][t].x, bf[s & 1][t].y);
                }
            }
        }
    }

    // ---------- epilogue: +bias, store fp32 ----------
#pragma unroll
    for (int mt = 0; mt < MT; mt++)
#pragma unroll
        for (int t = 0; t < 8; t++) {
            int gcol = n0 + t * 8 + (lane & 3) * 2;
            float2 bv = *(const float2*)&bb[gcol];
            int r0 = row0 + wrow + mt * 16 + (lane >> 2);
            float2 v0 = { acc[mt][t][0] + bv.x, acc[mt][t][1] + bv.y };
            float2 v1 = { acc[mt][t][2] + bv.x, acc[mt][t][3] + bv.y };
            *(float2*)&out[(size_t)r0 * fout + gcol]       = v0;
            *(float2*)&out[(size_t)(r0 + 8) * fout + gcol] = v1;
        }
}

// ---------------------------------------------------------------------------
// 4) BN batch stats
// ---------------------------------------------------------------------------
__global__ void bn_stats_kernel(const float* __restrict__ conv,
                                float* __restrict__ bn,
                                int N, int fout, int rows_per_block)
{
    __shared__ float r1[256];
    __shared__ float r2[256];
    int t   = threadIdx.x;
    int o   = t % fout;
    int rl  = t / fout;
    int rpb = 256 / fout;
    int n0  = blockIdx.x * rows_per_block;
    int n1  = min(N, n0 + rows_per_block);
    float s = 0.f, s2 = 0.f;
    for (int n = n0 + rl; n < n1; n += rpb) {
        float v = conv[(size_t)n * fout + o];
        s += v; s2 += v * v;
    }
    r1[t] = s; r2[t] = s2;
    __syncthreads();
    for (int off = 128; off >= fout; off >>= 1) {
        if (t < off) { r1[t] += r1[t + off]; r2[t] += r2[t + off]; }
        __syncthreads();
    }
    if (t < fout) {
        atomicAdd(&bn[t],        r1[t]);
        atomicAdd(&bn[fout + t], r2[t]);
    }
}

// ---------------------------------------------------------------------------
// 5) BN apply + ReLU + 2x2 maxpool, output NCHW
// ---------------------------------------------------------------------------
__global__ void bn_pool_kernel(const float* __restrict__ conv,
                               const float* __restrict__ bn,
                               const float* __restrict__ gamma,
                               const float* __restrict__ beta,
                               float* __restrict__ xout,
                               int B, int fout, int H, int W)
{
    int H2 = H >> 1, W2 = W >> 1;
    int idx = blockIdx.x * blockDim.x + threadIdx.x;
    int total = B * fout * H2 * W2;
    if (idx >= total) return;
    int o = idx % fout;
    int r = idx / fout;
    int w2 = r % W2; r /= W2;
    int h2 = r % H2;
    int b  = r / H2;

    float cnt  = (float)(B * H * W);
    float mean = bn[o] / cnt;
    float var  = bn[fout + o] / cnt - mean * mean;
    float sc   = gamma[o] * rsqrtf(var + 1e-5f);
    float sh   = beta[o] - mean * sc;

    int h = h2 * 2, w = w2 * 2;
    size_t base = ((size_t)(b * H + h) * W + w) * fout + o;
    float v00 = conv[base];
    float v01 = conv[base + fout];
    float v10 = conv[base + (size_t)W * fout];
    float v11 = conv[base + (size_t)W * fout + fout];
    float mx = fmaxf(fmaxf(fmaxf(v00 * sc + sh, 0.f), fmaxf(v01 * sc + sh, 0.f)),
                     fmaxf(fmaxf(v10 * sc + sh, 0.f), fmaxf(v11 * sc + sh, 0.f)));
    xout[((size_t)(b * fout + o) * H2 + h2) * W2 + w2] = mx;
}

// ---------------------------------------------------------------------------
extern "C" void kernel_launch(void* const* d_in, const int* in_sizes, int n_in,
                              void* d_out, int out_size)
{
    (void)in_sizes; (void)n_in; (void)out_size;

    float *mu, *rstd, *conv, *x1, *x2, *bn;
    uint32_t* wtb;
    cudaGetSymbolAddress((void**)&mu,   g_mu);
    cudaGetSymbolAddress((void**)&rstd, g_rstd);
    cudaGetSymbolAddress((void**)&wtb,  g_wtb);
    cudaGetSymbolAddress((void**)&conv, g_conv);
    cudaGetSymbolAddress((void**)&x1,   g_x1);
    cudaGetSymbolAddress((void**)&x2,   g_x2);
    cudaGetSymbolAddress((void**)&bn,   g_bn);

    struct LCfg { int B, C, H, W, fin, fout; };
    const LCfg L[3] = {
        {32,  16, 64, 64,  144,  64},
        {32,  64, 32, 32,  576, 128},
        {32, 128, 16, 16, 1152, 256},
    };

    const float* xin = (const float*)d_in[0];
    for (int l = 0; l < 3; l++) {
        const float* lnw = (const float*)d_in[1 + 7 * l + 0];
        const float* lnb = (const float*)d_in[1 + 7 * l + 1];
        const float* Wb  = (const float*)d_in[1 + 7 * l + 2];
        const float* bbv = (const float*)d_in[1 + 7 * l + 3];
        const float* Ws  = (const float*)d_in[1 + 7 * l + 4];
        const float* gam = (const float*)d_in[1 + 7 * l + 5];
        const float* bet = (const float*)d_in[1 + 7 * l + 6];

        int B = L[l].B, C = L[l].C, H = L[l].H, W = L[l].W;
        int fin = L[l].fin, fout = L[l].fout;
        int N = B * H * W;

        prep_stats_kernel<<<(N + 7) / 8, 256>>>(xin, mu, rstd, C, H, W, fin, N);

        int wtot = fin * 14 * fout;
        wtrans_frag_kernel<<<(wtot + 255) / 256, 256>>>(Wb, Ws, wtb, fin, fout);

        dim3 g(N / 128, fout / 64);
        if (l < 2) {
            kan_mma_kernel<32><<<g, 128>>>(xin, mu, rstd, lnw, lnb, wtb, bbv,
                                           conv, C, H, W, fin, fout);
        } else {
            kan_mma_kernel<16><<<g, 256>>>(xin, mu, rstd, lnw, lnb, wtb, bbv,
                                           conv, C, H, W, fin, fout);
        }

        cudaMemsetAsync(bn, 0, 2 * fout * sizeof(float), 0);
        bn_stats_kernel<<<(N + 511) / 512, 256>>>(conv, bn, N, fout, 512);

        float* xout = (l == 0) ? x1 : (l == 1) ? x2 : (float*)d_out;
        int tot = B * fout * (H / 2) * (W / 2);
        bn_pool_kernel<<<(tot + 255) / 256, 256>>>(conv, bn, gam, bet, xout,
                                                   B, fout, H, W);
        xin = xout;
    }
}

// round 17
// speedup vs baseline: 1.4094x; 1.4094x over previous
#include <cuda_runtime.h>
#include <cuda_bf16.h>
#include <math.h>
#include <stdint.h>

// ---------------------------------------------------------------------------
// FastKAN 3-layer conv net — HMMA (mma.sync bf16), warp-independent.
// R17 = R15 (best: 1723us) exactly, + bn_stats launched with 4x more CTAs
// (rows_per_block 512 -> 128) to fix its latency-bound 21us/layer profile.
// ---------------------------------------------------------------------------

#define MAXF_STAT (131072)
#define MAXF_CONV (131072 * 64)
#define MAXF_X1   (32 * 64 * 32 * 32)
#define MAXF_X2   (32 * 128 * 16 * 16)
#define MAX_WTB32 (1152 * 16 * 256)

__device__ float g_mu[MAXF_STAT];
__device__ float g_rstd[MAXF_STAT];
__device__ uint32_t g_wtb[MAX_WTB32];
__device__ float g_conv[MAXF_CONV];
__device__ float g_x1[MAXF_X1];
__device__ float g_x2[MAXF_X2];
__device__ float g_bn[2 * 256];

// ------------------------------ helpers -----------------------------------
__device__ __forceinline__ uint32_t s2u(const void* p) {
    uint32_t a;
    asm("{ .reg .u64 t; cvta.to.shared.u64 t, %1; cvt.u32.u64 %0, t; }"
        : "=r"(a) : "l"(p));
    return a;
}
__device__ __forceinline__ void ldmatrix_x4(uint32_t* r, uint32_t addr) {
    asm volatile("ldmatrix.sync.aligned.m8n8.x4.shared.b16 {%0,%1,%2,%3}, [%4];"
                 : "=r"(r[0]), "=r"(r[1]), "=r"(r[2]), "=r"(r[3]) : "r"(addr));
}
__device__ __forceinline__ void mma16816(float* c, const uint32_t* a,
                                         uint32_t b0, uint32_t b1) {
    asm volatile(
        "mma.sync.aligned.m16n8k16.row.col.f32.bf16.bf16.f32 "
        "{%0,%1,%2,%3}, {%4,%5,%6,%7}, {%8,%9}, {%0,%1,%2,%3};"
        : "+f"(c[0]), "+f"(c[1]), "+f"(c[2]), "+f"(c[3])
        : "r"(a[0]), "r"(a[1]), "r"(a[2]), "r"(a[3]), "r"(b0), "r"(b1));
}

// ---------------------------------------------------------------------------
// 1) per-pixel LayerNorm stats only (mu, rstd). One warp per pixel.
// ---------------------------------------------------------------------------
__global__ void prep_stats_kernel(const float* __restrict__ x,
                                  float* __restrict__ mu_o,
                                  float* __restrict__ rstd_o,
                                  int C, int H, int W, int fin, int N)
{
    int warp = (blockIdx.x * blockDim.x + threadIdx.x) >> 5;
    int lane = threadIdx.x & 31;
    if (warp >= N) return;
    int w = warp % W;
    int h = (warp / W) % H;
    int b = warp / (W * H);
    const float* xb = x + (size_t)b * C * H * W;

    float s = 0.f, s2 = 0.f;
    for (int f = lane; f < fin; f += 32) {
        int c = f / 9, r = f - c * 9;
        int hh = h + r / 3 - 1, ww = w + (r % 3) - 1;
        float v = 0.f;
        if (hh >= 0 && hh < H && ww >= 0 && ww < W)
            v = xb[(c * H + hh) * W + ww];
        s += v; s2 += v * v;
    }
#pragma unroll
    for (int o = 16; o; o >>= 1) {
        s  += __shfl_xor_sync(0xffffffffu, s,  o);
        s2 += __shfl_xor_sync(0xffffffffu, s2, o);
    }
    if (lane == 0) {
        float inv  = 1.f / (float)fin;
        float mu   = s * inv;
        float var  = fmaxf(s2 * inv - mu * mu, 0.f);
        mu_o[warp]   = mu;
        rstd_o[warp] = rsqrtf(var + 1e-5f);
    }
}

// ---------------------------------------------------------------------------
// 2) weight prep: pack B in HMMA fragment order (32-slot padded K).
// ---------------------------------------------------------------------------
__global__ void wtrans_frag_kernel(const float* __restrict__ Wb,
                                   const float* __restrict__ Ws,
                                   uint32_t* __restrict__ wtb,
                                   int fin, int fout)
{
    int idx = blockIdx.x * blockDim.x + threadIdx.x;
    int nt = fout >> 3;
    int total = fin * 16 * fout;
    if (idx >= total) return;
    int r  = idx & 1;
    int l  = (idx >> 1) & 31;
    int tg = (idx >> 6) % nt;
    int cs = idx / (64 * nt);
    int n  = tg * 8 + (l >> 2);
    int k0 = cs * 16 + (l & 3) * 2 + r * 8;

    float f2[2];
#pragma unroll
    for (int e = 0; e < 2; e++) {
        int k = k0 + e;
        int i = k >> 5, slot = k & 31;
        float v = 0.f;
        if (slot < 27) {
            int t9 = slot / 3, term = slot % 3;
            float w = (t9 == 0) ? Wb[(size_t)n * fin + i]
                                : Ws[(size_t)n * fin * 8 + i * 8 + (t9 - 1)];
            __nv_bfloat16 h = __float2bfloat16(w);
            v = (term == 1) ? (w - __bfloat162float(h)) : __bfloat162float(h);
        }
        f2[e] = v;
    }
    __nv_bfloat162 p;
    p.x = __float2bfloat16(f2[0]);
    p.y = __float2bfloat16(f2[1]);
    wtb[idx] = *(uint32_t*)&p;
}

// ---------------------------------------------------------------------------
// 3) fused KAN HMMA kernel — warp-independent, prep fused, templated M tile.
//    MROWS=32: 128-thread CTAs, warp owns 32 rows (2 m16 tiles, shared B).
//    MROWS=16: 256-thread CTAs, warp owns 16 rows.
//    CTA always covers 128 rows x 64 cols.
// ---------------------------------------------------------------------------
template<int MROWS>
__global__ __launch_bounds__(4096 / MROWS, MROWS == 32 ? 4 : 2)
void kan_mma_kernel(const float* __restrict__ x,
                    const float* __restrict__ mu_a,
                    const float* __restrict__ rstd_a,
                    const float* __restrict__ lnw,
                    const float* __restrict__ lnb,
                    const uint32_t* __restrict__ wtb,
                    const float* __restrict__ bb,
                    float* __restrict__ out,
                    int Cin, int H, int W, int fin, int fout)
{
    constexpr int MT = MROWS / 16;           // m16 tiles per warp
    __shared__ __align__(1024) char As[128 * 128];   // 16 KB

    int tid  = threadIdx.x;
    int lane = tid & 31;
    int wid  = tid >> 5;
    int row0 = blockIdx.x * 128;
    int n0   = blockIdx.y * 64;
    int wrow = wid * MROWS;
    int ntglob = fout >> 3;
    int n0g = n0 >> 3;
    uint32_t Ab = s2u(As);

    float acc[MT][8][4];
#pragma unroll
    for (int mt = 0; mt < MT; mt++)
#pragma unroll
        for (int t = 0; t < 8; t++)
#pragma unroll
            for (int q = 0; q < 4; q++) acc[mt][t][q] = 0.f;

    // expansion task: fixed pixel per thread.
    int erow  = (MROWS == 32) ? lane : (lane & 15);
    int fbase = (MROWS == 32) ? 0    : (lane >> 4);
    int m    = wrow + erow;
    int npix = row0 + m;
    int wpix = npix % W;
    int hpix = (npix / W) % H;
    int bpix = npix / (W * H);
    float mu_v = mu_a[npix];
    float rs_v = rstd_a[npix];
    const float* xb = x + (size_t)bpix * Cin * H * W;

    int j = lane >> 3, rr2 = lane & 7;
    int C = fin >> 1;            // chunks (2 features each)

    auto gather = [&](int f) -> float {
        int cch = f / 9, r = f - cch * 9;
        int hh = hpix + r / 3 - 1, ww = wpix + (r % 3) - 1;
        float v = 0.f;
        if (hh >= 0 && hh < H && ww >= 0 && ww < W)
            v = xb[(cch * H + hh) * W + ww];
        return v;
    };

    float v_next[MT];
#pragma unroll
    for (int fi = 0; fi < MT; fi++)
        v_next[fi] = gather((MROWS == 32) ? fi : fbase);

    for (int c = 0; c < C; c++) {
        // ---------- expand chunk c into own A slice ----------
#pragma unroll
        for (int fi = 0; fi < MT; fi++) {
            int fl = (MROWS == 32) ? fi : fbase;
            int f  = 2 * c + fl;
            float v  = v_next[fi];
            float xv = (v - mu_v) * rs_v * __ldg(&lnw[f]) + __ldg(&lnb[f]);
            float sv = v / (1.f + __expf(-v));

            const float q = 0.13533528323661270f;   // exp(-2)
            float d  = fmaf(xv, 1.75f, -0.5f);       // u-4, u=1.75x+3.5
            float e4 = __expf(-d * d);
            float R  = __expf(fmaf( 2.f, d, -1.f));
            float S  = __expf(fmaf(-2.f, d, -1.f));
            float e5 = e4 * R;  R *= q;
            float e6 = e5 * R;  R *= q;
            float e7 = e6 * R;
            float e3 = e4 * S;  S *= q;
            float e2 = e3 * S;  S *= q;
            float e1 = e2 * S;  S *= q;
            float e0 = e1 * S;

            float vals[9] = { sv, e0, e1, e2, e3, e4, e5, e6, e7 };

            uint32_t vb[9], lb[9];
#pragma unroll
            for (int t9 = 0; t9 < 9; t9++) {
                uint32_t b = __float_as_uint(vals[t9]);
                vb[t9] = b;
                float hf = __uint_as_float(b & 0xFFFF0000u);
                lb[t9] = (uint32_t)__bfloat16_as_ushort(
                             __float2bfloat16(vals[t9] - hf));
            }
            uint32_t wpk[16];
#pragma unroll
            for (int p = 0; p < 4; p++) {
                wpk[3 * p + 0] = __byte_perm(vb[2 * p],     vb[2 * p],     0x3232);
                wpk[3 * p + 1] = __byte_perm(lb[2 * p],     vb[2 * p + 1], 0x7610);
                wpk[3 * p + 2] = __byte_perm(vb[2 * p + 1], lb[2 * p + 1], 0x5432);
            }
            wpk[12] = __byte_perm(vb[8], vb[8], 0x3232);
            wpk[13] = lb[8];
            wpk[14] = 0u;
            wpk[15] = 0u;

#pragma unroll
            for (int j2 = 0; j2 < 4; j2++) {
                uint32_t col = (uint32_t)((fl * 4 + j2) ^ (m & 7));
                uint32_t ad  = Ab + (uint32_t)m * 128 + col * 16;
                asm volatile("st.shared.v4.b32 [%0], {%1,%2,%3,%4};"
                             :: "r"(ad), "r"(wpk[4 * j2]), "r"(wpk[4 * j2 + 1]),
                                "r"(wpk[4 * j2 + 2]), "r"(wpk[4 * j2 + 3]));
            }
        }
        __syncwarp();
        // prefetch next chunk's taps; MMA below covers their latency
        if (c + 1 < C) {
#pragma unroll
            for (int fi = 0; fi < MT; fi++)
                v_next[fi] = gather(2 * (c + 1) + ((MROWS == 32) ? fi : fbase));
        }
        // ---------- MMA chunk c (B double buffer; B reused across MT tiles) --
        {
            uint2 bf[2][8];
            {
                const uint2* bp = (const uint2*)wtb
                                + ((size_t)(c * 4) * ntglob + n0g) * 32 + lane;
#pragma unroll
                for (int t = 0; t < 8; t++) bf[0][t] = __ldg(bp + t * 32);
            }
#pragma unroll
            for (int s = 0; s < 4; s++) {
                if (s < 3) {
                    const uint2* bp = (const uint2*)wtb
                                    + ((size_t)(c * 4 + s + 1) * ntglob + n0g) * 32 + lane;
#pragma unroll
                    for (int t = 0; t < 8; t++) bf[(s + 1) & 1][t] = __ldg(bp + t * 32);
                }
#pragma unroll
                for (int mt = 0; mt < MT; mt++) {
                    uint32_t af[4];
                    int arow = wrow + mt * 16 + (j & 1) * 8 + rr2;
                    int acol = (s * 2 + (j >> 1)) ^ (arow & 7);
                    ldmatrix_x4(af, Ab + (uint32_t)arow * 128 + (uint32_t)acol * 16);
#pragma unroll
                    for (int t = 0; t < 8; t++)
                        mma16816(acc[mt][t], af, bf[s & 1][t].x, bf[s & 1][t].y);
                }
            }
        }
    }

    // ---------- epilogue: +bias, store fp32 ----------
#pragma unroll
    for (int mt = 0; mt < MT; mt++)
#pragma unroll
        for (int t = 0; t < 8; t++) {
            int gcol = n0 + t * 8 + (lane & 3) * 2;
            float2 bv = *(const float2*)&bb[gcol];
            int r0 = row0 + wrow + mt * 16 + (lane >> 2);
            float2 v0 = { acc[mt][t][0] + bv.x, acc[mt][t][1] + bv.y };
            float2 v1 = { acc[mt][t][2] + bv.x, acc[mt][t][3] + bv.y };
            *(float2*)&out[(size_t)r0 * fout + gcol]       = v0;
            *(float2*)&out[(size_t)(r0 + 8) * fout + gcol] = v1;
        }
}

// ---------------------------------------------------------------------------
// 4) BN batch stats (R17: 4x more CTAs — latency-bound before)
// ---------------------------------------------------------------------------
__global__ void bn_stats_kernel(const float* __restrict__ conv,
                                float* __restrict__ bn,
                                int N, int fout, int rows_per_block)
{
    __shared__ float r1[256];
    __shared__ float r2[256];
    int t   = threadIdx.x;
    int o   = t % fout;
    int rl  = t / fout;
    int rpb = 256 / fout;
    int n0  = blockIdx.x * rows_per_block;
    int n1  = min(N, n0 + rows_per_block);
    float s = 0.f, s2 = 0.f;
    for (int n = n0 + rl; n < n1; n += rpb) {
        float v = conv[(size_t)n * fout + o];
        s += v; s2 += v * v;
    }
    r1[t] = s; r2[t] = s2;
    __syncthreads();
    for (int off = 128; off >= fout; off >>= 1) {
        if (t < off) { r1[t] += r1[t + off]; r2[t] += r2[t + off]; }
        __syncthreads();
    }
    if (t < fout) {
        atomicAdd(&bn[t],        r1[t]);
        atomicAdd(&bn[fout + t], r2[t]);
    }
}

// ---------------------------------------------------------------------------
// 5) BN apply + ReLU + 2x2 maxpool, output NCHW
// ---------------------------------------------------------------------------
__global__ void bn_pool_kernel(const float* __restrict__ conv,
                               const float* __restrict__ bn,
                               const float* __restrict__ gamma,
                               const float* __restrict__ beta,
                               float* __restrict__ xout,
                               int B, int fout, int H, int W)
{
    int H2 = H >> 1, W2 = W >> 1;
    int idx = blockIdx.x * blockDim.x + threadIdx.x;
    int total = B * fout * H2 * W2;
    if (idx >= total) return;
    int o = idx % fout;
    int r = idx / fout;
    int w2 = r % W2; r /= W2;
    int h2 = r % H2;
    int b  = r / H2;

    float cnt  = (float)(B * H * W);
    float mean = bn[o] / cnt;
    float var  = bn[fout + o] / cnt - mean * mean;
    float sc   = gamma[o] * rsqrtf(var + 1e-5f);
    float sh   = beta[o] - mean * sc;

    int h = h2 * 2, w = w2 * 2;
    size_t base = ((size_t)(b * H + h) * W + w) * fout + o;
    float v00 = conv[base];
    float v01 = conv[base + fout];
    float v10 = conv[base + (size_t)W * fout];
    float v11 = conv[base + (size_t)W * fout + fout];
    float mx = fmaxf(fmaxf(fmaxf(v00 * sc + sh, 0.f), fmaxf(v01 * sc + sh, 0.f)),
                     fmaxf(fmaxf(v10 * sc + sh, 0.f), fmaxf(v11 * sc + sh, 0.f)));
    xout[((size_t)(b * fout + o) * H2 + h2) * W2 + w2] = mx;
}

// ---------------------------------------------------------------------------
extern "C" void kernel_launch(void* const* d_in, const int* in_sizes, int n_in,
                              void* d_out, int out_size)
{
    (void)in_sizes; (void)n_in; (void)out_size;

    float *mu, *rstd, *conv, *x1, *x2, *bn;
    uint32_t* wtb;
    cudaGetSymbolAddress((void**)&mu,   g_mu);
    cudaGetSymbolAddress((void**)&rstd, g_rstd);
    cudaGetSymbolAddress((void**)&wtb,  g_wtb);
    cudaGetSymbolAddress((void**)&conv, g_conv);
    cudaGetSymbolAddress((void**)&x1,   g_x1);
    cudaGetSymbolAddress((void**)&x2,   g_x2);
    cudaGetSymbolAddress((void**)&bn,   g_bn);

    struct LCfg { int B, C, H, W, fin, fout; };
    const LCfg L[3] = {
        {32,  16, 64, 64,  144,  64},
        {32,  64, 32, 32,  576, 128},
        {32, 128, 16, 16, 1152, 256},
    };

    const float* xin = (const float*)d_in[0];
    for (int l = 0; l < 3; l++) {
        const float* lnw = (const float*)d_in[1 + 7 * l + 0];
        const float* lnb = (const float*)d_in[1 + 7 * l + 1];
        const float* Wb  = (const float*)d_in[1 + 7 * l + 2];
        const float* bbv = (const float*)d_in[1 + 7 * l + 3];
        const float* Ws  = (const float*)d_in[1 + 7 * l + 4];
        const float* gam = (const float*)d_in[1 + 7 * l + 5];
        const float* bet = (const float*)d_in[1 + 7 * l + 6];

        int B = L[l].B, C = L[l].C, H = L[l].H, W = L[l].W;
        int fin = L[l].fin, fout = L[l].fout;
        int N = B * H * W;

        prep_stats_kernel<<<(N + 7) / 8, 256>>>(xin, mu, rstd, C, H, W, fin, N);

        int wtot = fin * 16 * fout;
        wtrans_frag_kernel<<<(wtot + 255) / 256, 256>>>(Wb, Ws, wtb, fin, fout);

        dim3 g(N / 128, fout / 64);
        if (l < 2) {
            kan_mma_kernel<32><<<g, 128>>>(xin, mu, rstd, lnw, lnb, wtb, bbv,
                                           conv, C, H, W, fin, fout);
        } else {
            kan_mma_kernel<16><<<g, 256>>>(xin, mu, rstd, lnw, lnb, wtb, bbv,
                                           conv, C, H, W, fin, fout);
        }

        cudaMemsetAsync(bn, 0, 2 * fout * sizeof(float), 0);
        bn_stats_kernel<<<(N + 127) / 128, 256>>>(conv, bn, N, fout, 128);

        float* xout = (l == 0) ? x1 : (l == 1) ? x2 : (float*)d_out;
        int tot = B * fout * (H / 2) * (W / 2);
        bn_pool_kernel<<<(tot + 255) / 256, 256>>>(conv, bn, gam, bet, xout,
                                                   B, fout, H, W);
        xin = xout;
    }
}